// round 1
// baseline (speedup 1.0000x reference)
#include <cuda_runtime.h>
#include <math_constants.h>

// ---------------------------------------------------------------------------
// Net_40312563041045: 4-layer max-tempered MLP
//   h = 0.8 * (X @ W^T) + 0.2 * max_k(W[o,k] * x[b,k]) + b
// Shapes: B=1024, 256 -> 512 -> 512 -> 512 -> 1, fp32.
// ---------------------------------------------------------------------------

#define BETA 0.2f

// Tiling for the main layer kernel
#define BM 64
#define BN 32
#define BK 32
#define TM 4
#define TN 2
// threads = (BM/TM)*(BN/TN) = 16*16 = 256

// Intermediate activation ping-pong buffers (no cudaMalloc allowed)
__device__ float g_h1[1024 * 512];
__device__ float g_h2[1024 * 512];

template <int K>
__global__ void __launch_bounds__(256)
layer_kernel(const float* __restrict__ X,   // [B, K] row-major
             const float* __restrict__ W,   // [O, K] row-major
             const float* __restrict__ bias,// [O]
             float* __restrict__ H,         // [B, O]
             int O)
{
    __shared__ float Xs[BM][BK + 1];  // +1 pad: conflict-free reads/writes
    __shared__ float Ws[BN][BK + 1];

    const int tid  = threadIdx.x;
    const int tcol = tid & 15;   // 0..15 -> output-col group (TN=2 each)
    const int trow = tid >> 4;   // 0..15 -> output-row group (TM=4 each)
    const int m0   = blockIdx.x * BM;
    const int n0   = blockIdx.y * BN;

    float acc[TM][TN];
    float mx [TM][TN];
#pragma unroll
    for (int i = 0; i < TM; i++)
#pragma unroll
        for (int j = 0; j < TN; j++) {
            acc[i][j] = 0.0f;
            mx [i][j] = -CUDART_INF_F;
        }

    const int lk = tid & (BK - 1); // lane along K for loads
    const int lr = tid >> 5;       // 0..7 row group for loads

    for (int k0 = 0; k0 < K; k0 += BK) {
        // Stage X tile (BM x BK): coalesced 128B rows, conflict-free STS
#pragma unroll
        for (int p = 0; p < BM / 8; ++p) {
            int m = lr + p * 8;
            Xs[m][lk] = X[(size_t)(m0 + m) * K + k0 + lk];
        }
        // Stage W tile (BN x BK)
#pragma unroll
        for (int p = 0; p < BN / 8; ++p) {
            int n = lr + p * 8;
            Ws[n][lk] = W[(size_t)(n0 + n) * K + k0 + lk];
        }
        __syncthreads();

#pragma unroll
        for (int k = 0; k < BK; ++k) {
            float xv[TM], wv[TN];
#pragma unroll
            for (int i = 0; i < TM; i++) xv[i] = Xs[trow * TM + i][k];
#pragma unroll
            for (int j = 0; j < TN; j++) wv[j] = Ws[tcol * TN + j][k];
#pragma unroll
            for (int i = 0; i < TM; i++)
#pragma unroll
                for (int j = 0; j < TN; j++) {
                    float p = xv[i] * wv[j];
                    acc[i][j] += p;
                    mx[i][j] = fmaxf(mx[i][j], p);
                }
        }
        __syncthreads();
    }

#pragma unroll
    for (int i = 0; i < TM; i++) {
        int m = m0 + trow * TM + i;
#pragma unroll
        for (int j = 0; j < TN; j++) {
            int n = n0 + tcol * TN + j;
            H[(size_t)m * O + n] = (1.0f - BETA) * acc[i][j] + BETA * mx[i][j] + bias[n];
        }
    }
}

// Final layer: O = 1, K = 512. One warp per batch row.
__global__ void __launch_bounds__(256)
layer4_kernel(const float* __restrict__ X,   // [B, 512]
              const float* __restrict__ W,   // [512]
              const float* __restrict__ bias,// [1]
              float* __restrict__ out,       // [B]
              int B)
{
    const int warps_per_block = blockDim.x >> 5;
    const int row  = blockIdx.x * warps_per_block + (threadIdx.x >> 5);
    const int lane = threadIdx.x & 31;
    if (row >= B) return;

    float acc = 0.0f;
    float mx  = -CUDART_INF_F;
    const float* xr = X + (size_t)row * 512;
#pragma unroll
    for (int k = lane; k < 512; k += 32) {
        float p = W[k] * xr[k];
        acc += p;
        mx = fmaxf(mx, p);
    }
#pragma unroll
    for (int o = 16; o > 0; o >>= 1) {
        acc += __shfl_xor_sync(0xffffffff, acc, o);
        mx = fmaxf(mx, __shfl_xor_sync(0xffffffff, mx, o));
    }
    if (lane == 0)
        out[row] = (1.0f - BETA) * acc + BETA * mx + bias[0];
}

extern "C" void kernel_launch(void* const* d_in, const int* in_sizes, int n_in,
                              void* d_out, int out_size)
{
    const float* x  = (const float*)d_in[0];
    const float* W1 = (const float*)d_in[1];
    const float* b1 = (const float*)d_in[2];
    const float* W2 = (const float*)d_in[3];
    const float* b2 = (const float*)d_in[4];
    const float* W3 = (const float*)d_in[5];
    const float* b3 = (const float*)d_in[6];
    const float* W4 = (const float*)d_in[7];
    const float* b4 = (const float*)d_in[8];
    float* out = (float*)d_out;

    // Derive shapes (expected: B=1024, IN=256, WID=512)
    const int WID = in_sizes[2];               // 512
    const int IN  = in_sizes[1] / WID;         // 256
    const int B   = in_sizes[0] / IN;          // 1024

    float* h1 = nullptr;
    float* h2 = nullptr;
    cudaGetSymbolAddress((void**)&h1, g_h1);
    cudaGetSymbolAddress((void**)&h2, g_h2);

    dim3 block(256);
    dim3 grid1(B / BM, WID / BN);

    // Layer 1: [B,256] x [512,256] -> h1 [B,512]
    layer_kernel<256><<<grid1, block>>>(x, W1, b1, h1, WID);
    // Layer 2: [B,512] x [512,512] -> h2
    layer_kernel<512><<<grid1, block>>>(h1, W2, b2, h2, WID);
    // Layer 3: [B,512] x [512,512] -> h1 (reuse)
    layer_kernel<512><<<grid1, block>>>(h2, W3, b3, h1, WID);
    // Layer 4: [B,512] x [1,512] -> out [B]
    const int rows_per_block = 256 / 32;
    layer4_kernel<<<(B + rows_per_block - 1) / rows_per_block, block>>>(h1, W4, b4, out, B);
}

// round 2
// speedup vs baseline: 1.2106x; 1.2106x over previous
#include <cuda_runtime.h>
#include <math_constants.h>

// ---------------------------------------------------------------------------
// Net_40312563041045: 4-layer max-tempered MLP
//   h = 0.8 * (X @ W^T) + 0.2 * max_k(W[o,k] * x[b,k]) + b
// Shapes: B=1024, 256 -> 512 -> 512 -> 512 -> 1, fp32.
//
// R2: packed f32x2 math (mul.rn.f32x2 + add.rn.f32x2) halves fma-pipe
// instructions; FMNMX on the alu pipe balances. 64x64 block tile, 4x4
// micro-tile, cp.async double-buffered staging, conflict-free LDS.128.
// ---------------------------------------------------------------------------

#define BETA 0.2f
#define BM 64
#define BN 64
#define BK 32
#define TM 4
#define TN 4
#define SROW (BK + 4)   // 36 floats = 144B row stride: 16B-aligned, conflict-free

// Intermediate activation ping-pong buffers (no cudaMalloc allowed)
__device__ float g_h1[1024 * 512];
__device__ float g_h2[1024 * 512];

__device__ __forceinline__ unsigned smem_u32(const void* p) {
    return (unsigned)__cvta_generic_to_shared(p);
}

__device__ __forceinline__ void cp16(unsigned dst, const void* src) {
    asm volatile("cp.async.ca.shared.global [%0], [%1], 16;\n" :: "r"(dst), "l"(src));
}

// One packed step: 2 products, 2 accumulates (fma pipe, 2 instrs),
// 2 maxes (alu pipe, 2 instrs).
__device__ __forceinline__ void mt_step(unsigned long long &acc, float &mx,
                                        unsigned long long x2, unsigned long long w2) {
    asm("{\n\t"
        ".reg .b64 p;\n\t"
        ".reg .f32 plo, phi;\n\t"
        "mul.rn.f32x2 p, %2, %3;\n\t"
        "add.rn.f32x2 %0, %0, p;\n\t"
        "mov.b64 {plo, phi}, p;\n\t"
        "max.f32 %1, %1, plo;\n\t"
        "max.f32 %1, %1, phi;\n\t"
        "}" : "+l"(acc), "+f"(mx) : "l"(x2), "l"(w2));
}

template <int K>
__global__ void __launch_bounds__(256, 1)
layer_kernel(const float* __restrict__ X,   // [B, K]
             const float* __restrict__ W,   // [O, K]
             const float* __restrict__ bias,// [O]
             float* __restrict__ H,         // [B, O]
             int O)
{
    __shared__ float Xs[2][BM][SROW];
    __shared__ float Ws[2][BN][SROW];

    const int tid  = threadIdx.x;
    const int tcol = tid & 15;    // n-group: outputs n0 + tcol + 16*j
    const int trow = tid >> 4;    // m-group: rows m0 + trow*TM + i
    const int m0 = blockIdx.x * BM;
    const int n0 = blockIdx.y * BN;

    // staging map: each thread copies two 16B chunks for X and for W
    const int srow = tid >> 3;       // 0..31
    const int sc   = (tid & 7) * 4;  // float col 0,4,...,28

    unsigned long long acc[TM][TN];
    float mx[TM][TN];
#pragma unroll
    for (int i = 0; i < TM; i++)
#pragma unroll
        for (int j = 0; j < TN; j++) { acc[i][j] = 0ull; mx[i][j] = -CUDART_INF_F; }

    const int NCH = K / BK;

    // prologue: stage chunk 0 into buffer 0
    {
        const float* xg = X + (size_t)(m0 + srow) * K + sc;
        const float* wg = W + (size_t)(n0 + srow) * K + sc;
        cp16(smem_u32(&Xs[0][srow][sc]),      xg);
        cp16(smem_u32(&Xs[0][srow + 32][sc]), xg + (size_t)32 * K);
        cp16(smem_u32(&Ws[0][srow][sc]),      wg);
        cp16(smem_u32(&Ws[0][srow + 32][sc]), wg + (size_t)32 * K);
        asm volatile("cp.async.commit_group;\n");
    }

    for (int c = 0; c < NCH; ++c) {
        const int buf = c & 1;
        if (c + 1 < NCH) {
            const int nb = buf ^ 1;
            const int k0 = (c + 1) * BK;
            const float* xg = X + (size_t)(m0 + srow) * K + k0 + sc;
            const float* wg = W + (size_t)(n0 + srow) * K + k0 + sc;
            cp16(smem_u32(&Xs[nb][srow][sc]),      xg);
            cp16(smem_u32(&Xs[nb][srow + 32][sc]), xg + (size_t)32 * K);
            cp16(smem_u32(&Ws[nb][srow][sc]),      wg);
            cp16(smem_u32(&Ws[nb][srow + 32][sc]), wg + (size_t)32 * K);
            asm volatile("cp.async.commit_group;\n");
            asm volatile("cp.async.wait_group 1;\n");
        } else {
            asm volatile("cp.async.wait_group 0;\n");
        }
        __syncthreads();

#pragma unroll
        for (int kk = 0; kk < BK; kk += 4) {
            ulonglong2 xp[TM];
            ulonglong2 wp[TN];
#pragma unroll
            for (int i = 0; i < TM; i++)
                xp[i] = *(const ulonglong2*)&Xs[buf][trow * TM + i][kk];
#pragma unroll
            for (int j = 0; j < TN; j++)
                wp[j] = *(const ulonglong2*)&Ws[buf][tcol + 16 * j][kk];
#pragma unroll
            for (int i = 0; i < TM; i++)
#pragma unroll
                for (int j = 0; j < TN; j++) {
                    mt_step(acc[i][j], mx[i][j], xp[i].x, wp[j].x);
                    mt_step(acc[i][j], mx[i][j], xp[i].y, wp[j].y);
                }
        }
        __syncthreads();
    }

    // epilogue
#pragma unroll
    for (int i = 0; i < TM; i++) {
        const int m = m0 + trow * TM + i;
#pragma unroll
        for (int j = 0; j < TN; j++) {
            const int n = n0 + tcol + 16 * j;
            float lo = __uint_as_float((unsigned)(acc[i][j] & 0xffffffffull));
            float hi = __uint_as_float((unsigned)(acc[i][j] >> 32));
            H[(size_t)m * O + n] = (1.0f - BETA) * (lo + hi) + BETA * mx[i][j] + bias[n];
        }
    }
}

// Final layer: O = 1, K = 512. One warp per batch row, float4 vectorized.
__global__ void __launch_bounds__(256)
layer4_kernel(const float* __restrict__ X,   // [B, 512]
              const float* __restrict__ W,   // [512]
              const float* __restrict__ bias,// [1]
              float* __restrict__ out,       // [B]
              int B)
{
    const int row  = blockIdx.x * 8 + (threadIdx.x >> 5);
    const int lane = threadIdx.x & 31;
    if (row >= B) return;

    const float4* xr = (const float4*)(X + (size_t)row * 512);
    const float4* wr = (const float4*)W;

    float acc = 0.0f;
    float mx  = -CUDART_INF_F;
#pragma unroll
    for (int it = 0; it < 4; ++it) {
        float4 x = xr[lane + 32 * it];
        float4 w = wr[lane + 32 * it];
        float p0 = x.x * w.x, p1 = x.y * w.y, p2 = x.z * w.z, p3 = x.w * w.w;
        acc += (p0 + p1) + (p2 + p3);
        mx = fmaxf(fmaxf(mx, fmaxf(p0, p1)), fmaxf(p2, p3));
    }
#pragma unroll
    for (int o = 16; o > 0; o >>= 1) {
        acc += __shfl_xor_sync(0xffffffff, acc, o);
        mx = fmaxf(mx, __shfl_xor_sync(0xffffffff, mx, o));
    }
    if (lane == 0)
        out[row] = (1.0f - BETA) * acc + BETA * mx + bias[0];
}

extern "C" void kernel_launch(void* const* d_in, const int* in_sizes, int n_in,
                              void* d_out, int out_size)
{
    const float* x  = (const float*)d_in[0];
    const float* W1 = (const float*)d_in[1];
    const float* b1 = (const float*)d_in[2];
    const float* W2 = (const float*)d_in[3];
    const float* b2 = (const float*)d_in[4];
    const float* W3 = (const float*)d_in[5];
    const float* b3 = (const float*)d_in[6];
    const float* W4 = (const float*)d_in[7];
    const float* b4 = (const float*)d_in[8];
    float* out = (float*)d_out;

    const int WID = in_sizes[2];               // 512
    const int IN  = in_sizes[1] / WID;         // 256
    const int B   = in_sizes[0] / IN;          // 1024

    float* h1 = nullptr;
    float* h2 = nullptr;
    cudaGetSymbolAddress((void**)&h1, g_h1);
    cudaGetSymbolAddress((void**)&h2, g_h2);

    dim3 block(256);
    dim3 grid(B / BM, WID / BN);   // 16 x 8 = 128 blocks

    layer_kernel<256><<<grid, block>>>(x,  W1, b1, h1, WID);
    layer_kernel<512><<<grid, block>>>(h1, W2, b2, h2, WID);
    layer_kernel<512><<<grid, block>>>(h2, W3, b3, h1, WID);
    layer4_kernel<<<B / 8, block>>>(h1, W4, b4, out, B);
}